// round 10
// baseline (speedup 1.0000x reference)
#include <cuda_runtime.h>

// Problem constants
#define NG 2048   // G
#define NC 16     // C
#define NM 16     // m
// exp(x/gamma) = ex2(x * 100 * log2(e));  gamma*ln(s) = lg2(s) * gamma*ln2
#define KEXP 144.2695040889f
#define KLOG 0.00693147180560f

typedef unsigned long long u64;

// Packed layouts: element [g*16 + j] = (val[b=2j], val[b=2j+1])
__device__ u64      g_Rt2[NG * 16];        // R (un-normalized; scale in g_max)
__device__ u64      g_Cv2[NC * NG * 16];   // Cv_pre
__device__ int      g_max[16][8];          // banked float-bit maxes (values >= 0)
// slots: iter i uses 3i (Cv max), 3i+1 (Hs max), 3i+2 (R max). Zero-init at
// load => scale 1.0; values are replay-idempotent (atomicMax of identical
// deterministic values), so no reset kernel is needed.
__device__ unsigned g_bar[8];              // monotonic epoch counters (no reset)

// ---- f32x2 helpers (sm_103a packed fp32) ----
__device__ __forceinline__ u64 pk(float x, float y) {
    u64 v; asm("mov.b64 %0, {%1,%2};" : "=l"(v) : "f"(x), "f"(y)); return v;
}
__device__ __forceinline__ float2 unpk(u64 v) {
    float2 r; asm("mov.b64 {%0,%1}, %2;" : "=f"(r.x), "=f"(r.y) : "l"(v)); return r;
}
__device__ __forceinline__ u64 mul2(u64 a, u64 b) {
    u64 c; asm("mul.rn.f32x2 %0, %1, %2;" : "=l"(c) : "l"(a), "l"(b)); return c;
}
__device__ __forceinline__ u64 fma2(u64 a, u64 b, u64 c) {
    u64 d; asm("fma.rn.f32x2 %0, %1, %2, %3;" : "=l"(d) : "l"(a), "l"(b), "l"(c)); return d;
}
__device__ __forceinline__ float ex2(float x) {
    float y; asm("ex2.approx.ftz.f32 %0, %1;" : "=f"(y) : "f"(x)); return y;
}
__device__ __forceinline__ float lg2(float x) {
    float y; asm("lg2.approx.f32 %0, %1;" : "=f"(y) : "f"(x)); return y;
}
__device__ __forceinline__ int ldcg(const int* p) {
    int v; asm volatile("ld.global.cg.b32 %0, [%1];" : "=r"(v) : "l"(p)); return v;
}

// ---------------------------------------------------------------------------
// scale = 1/max if max>1 else 1.  ld.cg: L2-direct (safe after in-kernel barrier).
__device__ __forceinline__ float get_scale(int slot) {
    int v = ldcg(&g_max[slot][0]);
    #pragma unroll
    for (int k = 1; k < 8; k++) v = max(v, ldcg(&g_max[slot][k]));
    float m = __int_as_float(v);
    return (m > 1.0f) ? __fdividef(1.0f, m) : 1.0f;
}

// warp->block max reduce + one atomicMax per block (no barrier).
__device__ __forceinline__ void block_max_atomic(float val, int slot) {
    int v = __float_as_int(val);   // valid ordering: all values non-negative
    #pragma unroll
    for (int o = 16; o > 0; o >>= 1) v = max(v, __shfl_xor_sync(0xffffffffu, v, o));
    __shared__ int s_red[8];
    if ((threadIdx.x & 31) == 0) s_red[threadIdx.x >> 5] = v;
    __syncthreads();
    if (threadIdx.x == 0) {
        int m = s_red[0];
        #pragma unroll
        for (int k = 1; k < 8; k++) m = max(m, s_red[k]);
        atomicMax(&g_max[slot][blockIdx.x & 7], m);
    }
}

// block max -> atomicMax -> 128-block barrier (monotonic epoch counter).
// Arrival atomicAdd is data-dependent on the atomicMax return, so any block
// observed as "arrived" has its max visible at L2.
__device__ __forceinline__ void block_max_barrier(float val, int slot, int barId) {
    int v = __float_as_int(val);
    #pragma unroll
    for (int o = 16; o > 0; o >>= 1) v = max(v, __shfl_xor_sync(0xffffffffu, v, o));
    __shared__ int s_bar[8];
    if ((threadIdx.x & 31) == 0) s_bar[threadIdx.x >> 5] = v;
    __syncthreads();
    if (threadIdx.x == 0) {
        int m = s_bar[0];
        #pragma unroll
        for (int k = 1; k < 8; k++) m = max(m, s_bar[k]);
        int old = atomicMax(&g_max[slot][blockIdx.x & 7], m);
        // opaque +0 keeps the dependency: our values are finite & <= ~1.1
        unsigned inc = 1u + ((unsigned)old > 0x7f800000u ? 1u : 0u);
        unsigned prev = atomicAdd(&g_bar[barId], inc);
        unsigned target = (prev & ~127u) + 128u;
        unsigned cur;
        do {
            asm volatile("ld.global.cg.u32 %0, [%1];" : "=r"(cur) : "l"(&g_bar[barId]));
        } while (cur < target);
    }
    __syncthreads();
}

// ---------------------------------------------------------------------------
// kA: one (c,g)-item pair per warp (half-warp each), f32x2 throughout.
// grid 2048 x 256 (16384 warps). FIRST: old R comes straight from x (scale 1).
template<bool FIRST>
__global__ void __launch_bounds__(256, 4)
kA(const int* __restrict__ I, const float* __restrict__ x, int slotR, int slotOut) {
    const int tid  = threadIdx.x;
    const int lane = tid & 31;
    const int hf   = lane >> 4;                   // item-of-pair selector
    const int j    = lane & 15;                   // b-pair index
    const int P    = blockIdx.x * 8 + (tid >> 5); // pair id

    float sR = FIRST ? 1.0f : get_scale(slotR);
    float s3 = sR * sR * sR;
    float kexp = s3 * KEXP;                       // scale folded into LSE constant
    u64  kexp2 = pk(kexp, kexp);

    int item = 2 * P + hf;
    const int4* ip = reinterpret_cast<const int4*>(I) + item * 6;
    int4 a0 = ip[0], a1 = ip[1], a2 = ip[2], a3 = ip[3], a4 = ip[4], a5 = ip[5];
    #define GA(i) (FIRST ? pk(x[2 * j * NG + (i)], x[(2 * j + 1) * NG + (i)]) \
                         : g_Rt2[(i) * 16 + j])
    u64 b0 = mul2(mul2(GA(a0.x), GA(a0.y)), GA(a0.z));
    u64 b1 = mul2(mul2(GA(a0.w), GA(a1.x)), GA(a1.y));
    u64 b2 = mul2(mul2(GA(a1.z), GA(a1.w)), GA(a2.x));
    u64 b3 = mul2(mul2(GA(a2.y), GA(a2.z)), GA(a2.w));
    u64 b4 = mul2(mul2(GA(a3.x), GA(a3.y)), GA(a3.z));
    u64 b5 = mul2(mul2(GA(a3.w), GA(a4.x)), GA(a4.y));
    u64 b6 = mul2(mul2(GA(a4.z), GA(a4.w)), GA(a5.x));
    u64 b7 = mul2(mul2(GA(a5.y), GA(a5.z)), GA(a5.w));
    #undef GA
    float2 c0 = unpk(b0), c1 = unpk(b1), c2 = unpk(b2), c3 = unpk(b3);
    float2 c4 = unpk(b4), c5 = unpk(b5), c6 = unpk(b6), c7 = unpk(b7);
    float mxx = fmaxf(fmaxf(fmaxf(c0.x, c1.x), fmaxf(c2.x, c3.x)),
                      fmaxf(fmaxf(c4.x, c5.x), fmaxf(c6.x, c7.x)));
    float mxy = fmaxf(fmaxf(fmaxf(c0.y, c1.y), fmaxf(c2.y, c3.y)),
                      fmaxf(fmaxf(c4.y, c5.y), fmaxf(c6.y, c7.y)));
    u64 mneg = pk(-mxx * kexp, -mxy * kexp);
    float sx = 0.0f, sy = 0.0f;
    {
        u64 t0 = fma2(b0, kexp2, mneg); float2 f0 = unpk(t0); sx += ex2(f0.x); sy += ex2(f0.y);
        u64 t1 = fma2(b1, kexp2, mneg); float2 f1 = unpk(t1); sx += ex2(f1.x); sy += ex2(f1.y);
        u64 t2 = fma2(b2, kexp2, mneg); float2 f2 = unpk(t2); sx += ex2(f2.x); sy += ex2(f2.y);
        u64 t3 = fma2(b3, kexp2, mneg); float2 f3 = unpk(t3); sx += ex2(f3.x); sy += ex2(f3.y);
        u64 t4 = fma2(b4, kexp2, mneg); float2 f4 = unpk(t4); sx += ex2(f4.x); sy += ex2(f4.y);
        u64 t5 = fma2(b5, kexp2, mneg); float2 f5 = unpk(t5); sx += ex2(f5.x); sy += ex2(f5.y);
        u64 t6 = fma2(b6, kexp2, mneg); float2 f6 = unpk(t6); sx += ex2(f6.x); sy += ex2(f6.y);
        u64 t7 = fma2(b7, kexp2, mneg); float2 f7 = unpk(t7); sx += ex2(f7.x); sy += ex2(f7.y);
    }
    float cvx = fmaf(lg2(sx), KLOG, mxx * s3);
    float cvy = fmaf(lg2(sy), KLOG, mxy * s3);
    g_Cv2[item * 16 + j] = pk(cvx, cvy);
    block_max_atomic(fmaxf(cvx, cvy), slotOut);
}

// ---------------------------------------------------------------------------
// kBC: matvec + LSE_m (kB), internal 128-block barrier for Hs-max, then the
// 2-way softor merge (kC) with hs in registers. IT==0 reads old R from x;
// IT==4 adds a second barrier for the final R-max and stores the output.
// grid 128 x 256 (one g-pair per warp; 128 blocks <= SM count -> all resident)
template<int IT>
__global__ void __launch_bounds__(256, 1)
kBC(const float* __restrict__ x, const float* __restrict__ W,
    float* __restrict__ out,
    int slotR, int slotCv, int slotHs, int slotRn, int barId) {
    const int tid  = threadIdx.x;
    const int lane = tid & 31;
    const int hf   = lane >> 4;
    const int j    = lane & 15;
    const int g    = 2 * (blockIdx.x * 8 + (tid >> 5)) + hf;

    // ws = softmax(W) rows, computed redundantly per block (trivial)
    __shared__ u64 ws2[NM * NC];
    if (tid < NM) {
        float mx = -1e30f;
        #pragma unroll
        for (int c = 0; c < NC; c++) mx = fmaxf(mx, W[tid * NC + c]);
        float e[NC]; float sum = 0.0f;
        #pragma unroll
        for (int c = 0; c < NC; c++) { e[c] = ex2((W[tid * NC + c] - mx) * 1.4426950409f); sum += e[c]; }
        float inv = __fdividef(1.0f, sum);
        #pragma unroll
        for (int c = 0; c < NC; c++) { float w = e[c] * inv; ws2[tid * NC + c] = pk(w, w); }
    }
    float sR = (IT == 0) ? 1.0f : get_scale(slotR);   // old-R scale (pre-barrier read)
    float s1 = get_scale(slotCv);
    __syncthreads();

    // ---- kB part: H = Ws @ Cv, hs = gamma*LSE_m (scale folded) ----
    u64 h[NM];
    #pragma unroll
    for (int m = 0; m < NM; m++) h[m] = 0ull;
    #pragma unroll
    for (int c = 0; c < NC; c++) {
        u64 cvc = g_Cv2[(c * NG + g) * 16 + j];
        #pragma unroll
        for (int m = 0; m < NM; m++) h[m] = fma2(ws2[m * NC + c], cvc, h[m]);
    }
    float2 hh[NM];
    #pragma unroll
    for (int m = 0; m < NM; m++) hh[m] = unpk(h[m]);
    float mxx = hh[0].x, mxy = hh[0].y;
    #pragma unroll
    for (int m = 1; m < NM; m++) { mxx = fmaxf(mxx, hh[m].x); mxy = fmaxf(mxy, hh[m].y); }
    float k1 = s1 * KEXP;
    u64 k12 = pk(k1, k1), mneg = pk(-mxx * k1, -mxy * k1);
    float sx = 0.0f, sy = 0.0f;
    #pragma unroll
    for (int m = 0; m < NM; m++) {
        u64 t = fma2(h[m], k12, mneg);
        float2 f = unpk(t);
        sx += ex2(f.x); sy += ex2(f.y);
    }
    float hsx = fmaf(lg2(sx), KLOG, mxx * s1);
    float hsy = fmaf(lg2(sy), KLOG, mxy * s1);

    // ---- Hs-max grid sync (in-kernel barrier; hs stays in registers) ----
    block_max_barrier(fmaxf(hsx, hsy), slotHs, barId);
    float s2 = get_scale(slotHs);

    // ---- kC part: 2-way softor merge ----
    float2 rr;
    if (IT == 0) rr = make_float2(x[2 * j * NG + g], x[(2 * j + 1) * NG + g]);
    else         rr = unpk(g_Rt2[g * 16 + j]);
    float ax = rr.x * sR, ay = rr.y * sR;
    float bx = hsx * s2,  by = hsy * s2;
    float Mx = fmaxf(ax, bx), mnx = fminf(ax, bx);
    float My = fmaxf(ay, by), mny = fminf(ay, by);
    float rx = fmaf(lg2(1.0f + ex2((mnx - Mx) * KEXP)), KLOG, Mx);
    float ry = fmaf(lg2(1.0f + ex2((mny - My) * KEXP)), KLOG, My);

    if (IT < 4) {
        g_Rt2[g * 16 + j] = pk(rx, ry);
        block_max_atomic(fmaxf(rx, ry), slotRn);   // consumed by next launch
    } else {
        // final iteration: second barrier for R-max, then scaled output store
        block_max_barrier(fmaxf(rx, ry), slotRn, barId + 1);
        float sF = get_scale(slotRn);
        out[(2 * j) * NG + g]     = rx * sF;
        out[(2 * j + 1) * NG + g] = ry * sF;
    }
}

// ---------------------------------------------------------------------------
extern "C" void kernel_launch(void* const* d_in, const int* in_sizes, int n_in,
                              void* d_out, int out_size) {
    const float* x = (const float*)d_in[0];   // (32, 2048) f32
    const float* W = (const float*)d_in[1];   // (16, 16) f32
    const int*   I = (const int*)  d_in[2];   // (16, 2048, 8, 3) i32
    float* out = (float*)d_out;               // (32, 2048) f32

    kA<true> <<<2048, 256>>>(I, x, /*slotR*/0, /*slotOut*/0);
    kBC<0>   <<<128,  256>>>(x, W, out,  0,  0,  1,  2, 0);
    kA<false><<<2048, 256>>>(I, x,  2,  3);
    kBC<1>   <<<128,  256>>>(x, W, out,  2,  3,  4,  5, 1);
    kA<false><<<2048, 256>>>(I, x,  5,  6);
    kBC<2>   <<<128,  256>>>(x, W, out,  5,  6,  7,  8, 2);
    kA<false><<<2048, 256>>>(I, x,  8,  9);
    kBC<3>   <<<128,  256>>>(x, W, out,  8,  9, 10, 11, 3);
    kA<false><<<2048, 256>>>(I, x, 11, 12);
    kBC<4>   <<<128,  256>>>(x, W, out, 11, 12, 13, 14, 4);   // uses bars 4 and 5
}

// round 11
// speedup vs baseline: 2.3365x; 2.3365x over previous
#include <cuda_runtime.h>

// Problem constants
#define NG 2048   // G
#define NC 16     // C
#define NM 16     // m
// exp(x/gamma) = ex2(x * 100 * log2(e));  gamma*ln(s) = lg2(s) * gamma*ln2
#define KEXP 144.2695040889f
#define KLOG 0.00693147180560f

typedef unsigned long long u64;

// Packed layouts: element [g*16 + j] = (val[b=2j], val[b=2j+1])
__device__ u64 g_Rt2[NG * 16];        // R (un-normalized; scale in g_max)
__device__ u64 g_Cv2[NC * NG * 16];   // Cv_pre
__device__ u64 g_Hs2[NG * 16];        // Hs_pre
__device__ int g_max[16][8];          // banked float-bit maxes (values >= 0)
// slots: iter i uses 3i (Cv), 3i+1 (Hs), 3i+2 (R). Zero at load => scale 1.0.
// Replay-idempotent: every replay atomicMax-es identical deterministic values.

// ---- PDL primitives ----
__device__ __forceinline__ void gdc_launch() {
    asm volatile("griddepcontrol.launch_dependents;");
}
__device__ __forceinline__ void gdc_wait() {
    asm volatile("griddepcontrol.wait;" ::: "memory");
}

// ---- f32x2 helpers (sm_103a packed fp32) ----
__device__ __forceinline__ u64 pk(float x, float y) {
    u64 v; asm("mov.b64 %0, {%1,%2};" : "=l"(v) : "f"(x), "f"(y)); return v;
}
__device__ __forceinline__ float2 unpk(u64 v) {
    float2 r; asm("mov.b64 {%0,%1}, %2;" : "=f"(r.x), "=f"(r.y) : "l"(v)); return r;
}
__device__ __forceinline__ u64 mul2(u64 a, u64 b) {
    u64 c; asm("mul.rn.f32x2 %0, %1, %2;" : "=l"(c) : "l"(a), "l"(b)); return c;
}
__device__ __forceinline__ u64 fma2(u64 a, u64 b, u64 c) {
    u64 d; asm("fma.rn.f32x2 %0, %1, %2, %3;" : "=l"(d) : "l"(a), "l"(b), "l"(c)); return d;
}
__device__ __forceinline__ float ex2(float x) {
    float y; asm("ex2.approx.ftz.f32 %0, %1;" : "=f"(y) : "f"(x)); return y;
}
__device__ __forceinline__ float lg2(float x) {
    float y; asm("lg2.approx.f32 %0, %1;" : "=f"(y) : "f"(x)); return y;
}

// ---------------------------------------------------------------------------
__device__ __forceinline__ float get_scale(int slot) {
    int v = g_max[slot][0];
    #pragma unroll
    for (int k = 1; k < 8; k++) v = max(v, g_max[slot][k]);
    float m = __int_as_float(v);
    return (m > 1.0f) ? __fdividef(1.0f, m) : 1.0f;
}

// warp->block max reduce, one atomicMax per block. All 256 threads must call.
__device__ __forceinline__ void block_max_atomic(float val, int slot) {
    int v = __float_as_int(val);   // valid ordering: all values non-negative
    #pragma unroll
    for (int o = 16; o > 0; o >>= 1) v = max(v, __shfl_xor_sync(0xffffffffu, v, o));
    __shared__ int s_red[8];
    if ((threadIdx.x & 31) == 0) s_red[threadIdx.x >> 5] = v;
    __syncthreads();
    if (threadIdx.x == 0) {
        int m = s_red[0];
        #pragma unroll
        for (int k = 1; k < 8; k++) m = max(m, s_red[k]);
        atomicMax(&g_max[slot][blockIdx.x & 7], m);
    }
}

// ---------------------------------------------------------------------------
// kA: one (c,g)-item pair per warp (half-warp each), f32x2 throughout.
// grid 2048 x 256. Index loads (immutable I) issue BEFORE gdc_wait.
__global__ void __launch_bounds__(256, 4)
kA(const int* __restrict__ I, const float* __restrict__ x,
   int first, int slotR, int slotOut) {
    const int tid  = threadIdx.x;
    const int lane = tid & 31;
    const int hf   = lane >> 4;                   // item-of-pair selector
    const int j    = lane & 15;                   // b-pair index
    const int P    = blockIdx.x * 8 + (tid >> 5); // pair id
    const int item = 2 * P + hf;

    // preamble: immutable index loads overlap predecessor's tail
    const int4* ip = reinterpret_cast<const int4*>(I) + item * 6;
    int4 a0 = ip[0], a1 = ip[1], a2 = ip[2], a3 = ip[3], a4 = ip[4], a5 = ip[5];
    int idx[24] = { a0.x,a0.y,a0.z,a0.w, a1.x,a1.y,a1.z,a1.w, a2.x,a2.y,a2.z,a2.w,
                    a3.x,a3.y,a3.z,a3.w, a4.x,a4.y,a4.z,a4.w, a5.x,a5.y,a5.z,a5.w };

    gdc_wait();   // predecessor (kC / none) complete + visible

    float sR = first ? 1.0f : get_scale(slotR);
    float s3 = sR * sR * sR;
    float kexp = s3 * KEXP;                       // scale folded into LSE constant
    u64  kexp2 = pk(kexp, kexp);

    u64 b[8];
    if (first) {
        #pragma unroll
        for (int s = 0; s < 8; s++) {
            u64 v0 = pk(x[2 * j * NG + idx[3 * s + 0]], x[(2 * j + 1) * NG + idx[3 * s + 0]]);
            u64 v1 = pk(x[2 * j * NG + idx[3 * s + 1]], x[(2 * j + 1) * NG + idx[3 * s + 1]]);
            u64 v2 = pk(x[2 * j * NG + idx[3 * s + 2]], x[(2 * j + 1) * NG + idx[3 * s + 2]]);
            b[s] = mul2(mul2(v0, v1), v2);
        }
    } else {
        #pragma unroll
        for (int s = 0; s < 8; s++) {
            u64 v0 = g_Rt2[idx[3 * s + 0] * 16 + j];
            u64 v1 = g_Rt2[idx[3 * s + 1] * 16 + j];
            u64 v2 = g_Rt2[idx[3 * s + 2] * 16 + j];
            b[s] = mul2(mul2(v0, v1), v2);
        }
    }

    float2 c[8];
    #pragma unroll
    for (int s = 0; s < 8; s++) c[s] = unpk(b[s]);
    float mxx = c[0].x, mxy = c[0].y;
    #pragma unroll
    for (int s = 1; s < 8; s++) { mxx = fmaxf(mxx, c[s].x); mxy = fmaxf(mxy, c[s].y); }
    u64 mneg = pk(-mxx * kexp, -mxy * kexp);
    float sx = 0.0f, sy = 0.0f;
    #pragma unroll
    for (int s = 0; s < 8; s++) {
        float2 f = unpk(fma2(b[s], kexp2, mneg));
        sx += ex2(f.x); sy += ex2(f.y);
    }
    float cvx = fmaf(lg2(sx), KLOG, mxx * s3);
    float cvy = fmaf(lg2(sy), KLOG, mxy * s3);
    g_Cv2[item * 16 + j] = pk(cvx, cvy);

    gdc_launch();                                 // main store done -> let kB launch
    block_max_atomic(fmaxf(cvx, cvy), slotOut);
}

// ---------------------------------------------------------------------------
// kB: one g-pair per warp; matvec over c + LSE over m, f32x2.
// grid 128 x 256. softmax(W) (immutable W) computed BEFORE gdc_wait.
__global__ void __launch_bounds__(256, 4)
kB(const float* __restrict__ W, int slotCv, int slotOut) {
    const int tid  = threadIdx.x;
    const int lane = tid & 31;
    const int hf   = lane >> 4;
    const int j    = lane & 15;
    const int g    = 2 * (blockIdx.x * 8 + (tid >> 5)) + hf;

    __shared__ u64 ws2[NM * NC];
    if (tid < NM) {                               // preamble: W is immutable
        float mx = -1e30f;
        #pragma unroll
        for (int cc = 0; cc < NC; cc++) mx = fmaxf(mx, W[tid * NC + cc]);
        float e[NC]; float sum = 0.0f;
        #pragma unroll
        for (int cc = 0; cc < NC; cc++) { e[cc] = ex2((W[tid * NC + cc] - mx) * 1.4426950409f); sum += e[cc]; }
        float inv = __fdividef(1.0f, sum);
        #pragma unroll
        for (int cc = 0; cc < NC; cc++) { float w = e[cc] * inv; ws2[tid * NC + cc] = pk(w, w); }
    }

    gdc_wait();                                   // kA complete + visible
    float s1 = get_scale(slotCv);
    __syncthreads();

    u64 h[NM];
    #pragma unroll
    for (int m = 0; m < NM; m++) h[m] = 0ull;
    #pragma unroll
    for (int cc = 0; cc < NC; cc++) {
        u64 cvc = g_Cv2[(cc * NG + g) * 16 + j];
        #pragma unroll
        for (int m = 0; m < NM; m++) h[m] = fma2(ws2[m * NC + cc], cvc, h[m]);
    }
    float2 hh[NM];
    #pragma unroll
    for (int m = 0; m < NM; m++) hh[m] = unpk(h[m]);
    float mxx = hh[0].x, mxy = hh[0].y;
    #pragma unroll
    for (int m = 1; m < NM; m++) { mxx = fmaxf(mxx, hh[m].x); mxy = fmaxf(mxy, hh[m].y); }
    float k1 = s1 * KEXP;                         // scale folded into LSE
    u64 k12 = pk(k1, k1), mneg = pk(-mxx * k1, -mxy * k1);
    float sx = 0.0f, sy = 0.0f;
    #pragma unroll
    for (int m = 0; m < NM; m++) {
        float2 f = unpk(fma2(h[m], k12, mneg));
        sx += ex2(f.x); sy += ex2(f.y);
    }
    float hsx = fmaf(lg2(sx), KLOG, mxx * s1);
    float hsy = fmaf(lg2(sy), KLOG, mxy * s1);
    g_Hs2[g * 16 + j] = pk(hsx, hsy);

    gdc_launch();
    block_max_atomic(fmaxf(hsx, hsy), slotOut);
}

// ---------------------------------------------------------------------------
// kC: elementwise 2-way softor merge (both b-halves per thread), R in place.
// grid 128 x 256 (32768 threads == NG*16)
__global__ void __launch_bounds__(256, 4)
kC(const float* __restrict__ x, int first, int slotR, int slotHs, int slotOut) {
    int t = blockIdx.x * blockDim.x + threadIdx.x;

    gdc_wait();                                   // kB complete + visible
    float sR = first ? 1.0f : get_scale(slotR);
    float s2 = get_scale(slotHs);

    float2 rr;
    if (first) {
        int g = t >> 4, jj = t & 15;
        rr = make_float2(x[2 * jj * NG + g], x[(2 * jj + 1) * NG + g]);
    } else {
        rr = unpk(g_Rt2[t]);
    }
    float2 hv = unpk(g_Hs2[t]);
    float ax = rr.x * sR, ay = rr.y * sR;
    float bx = hv.x * s2, by = hv.y * s2;
    float Mx = fmaxf(ax, bx), mnx = fminf(ax, bx);
    float My = fmaxf(ay, by), mny = fminf(ay, by);
    float rx = fmaf(lg2(1.0f + ex2((mnx - Mx) * KEXP)), KLOG, Mx);
    float ry = fmaf(lg2(1.0f + ex2((mny - My) * KEXP)), KLOG, My);
    g_Rt2[t] = pk(rx, ry);

    gdc_launch();
    block_max_atomic(fmaxf(rx, ry), slotOut);
}

// ---------------------------------------------------------------------------
// kOut: final scale + unpack back to (B, G); coalesced stores. grid 256 x 256
__global__ void __launch_bounds__(256, 4)
kOut(float* __restrict__ out, int slotR) {
    int t = blockIdx.x * blockDim.x + threadIdx.x;   // t = b*NG + g
    gdc_wait();
    float s = get_scale(slotR);
    int b = t >> 11, g = t & (NG - 1);
    float2 v = unpk(g_Rt2[g * 16 + (b >> 1)]);
    out[t] = ((b & 1) ? v.y : v.x) * s;
    gdc_launch();
}

// ---------------------------------------------------------------------------
// PDL launch helper: programmatic stream serialization on the legacy stream.
template <typename... A>
static inline void pdl(void (*kern)(A...), dim3 g, dim3 b, A... args) {
    cudaLaunchConfig_t cfg = {};
    cfg.gridDim = g;
    cfg.blockDim = b;
    cfg.dynamicSmemBytes = 0;
    cfg.stream = (cudaStream_t)0;                 // legacy default (captured)
    cudaLaunchAttribute at[1];
    at[0].id = cudaLaunchAttributeProgrammaticStreamSerialization;
    at[0].val.programmaticStreamSerializationAllowed = 1;
    cfg.attrs = at;
    cfg.numAttrs = 1;
    cudaLaunchKernelEx(&cfg, kern, args...);
}

extern "C" void kernel_launch(void* const* d_in, const int* in_sizes, int n_in,
                              void* d_out, int out_size) {
    const float* x = (const float*)d_in[0];   // (32, 2048) f32
    const float* W = (const float*)d_in[1];   // (16, 16) f32
    const int*   I = (const int*)  d_in[2];   // (16, 2048, 8, 3) i32
    float* out = (float*)d_out;               // (32, 2048) f32

    const dim3 B(256);
    // iter 0
    pdl(kA, dim3(2048), B, I, x, 1, 0, 0);
    pdl(kB, dim3(128),  B, W, 0, 1);
    pdl(kC, dim3(128),  B, x, 1, 0, 1, 2);
    // iters 1..4: slots 3i (Cv), 3i+1 (Hs), 3i+2 (R)
    for (int i = 1; i < 5; i++) {
        int sCv = 3 * i, sHs = 3 * i + 1, sRn = 3 * i + 2, sRp = 3 * i - 1;
        pdl(kA, dim3(2048), B, I, x, 0, sRp, sCv);
        pdl(kB, dim3(128),  B, W, sCv, sHs);
        pdl(kC, dim3(128),  B, x, 0, sRp, sHs, sRn);
    }
    pdl(kOut, dim3(256), B, out, 14);
}